// round 2
// baseline (speedup 1.0000x reference)
#include <cuda_runtime.h>

// EdgeHead: out[e] = MLP(LN([u, v, |u-v|, u*v])) for u=h[src[e]], v=h[dst[e]]
// Design: per block, stage LayerNormed feat tile [256 x 64 edges] in smem,
// then register-tiled GEMM vs W1 (smem), fused ReLU + W2 dot epilogue.

#define TE 64          // edges per tile
#define NTHREADS 128
#define SMEM_FLOATS (256*TE + 256*32 + 256 + 256 + 32 + 32)

__global__ __launch_bounds__(NTHREADS, 2)
void edgehead_kernel(const float* __restrict__ h,
                     const void* __restrict__ ep_raw,
                     const float* __restrict__ gamma,
                     const float* __restrict__ beta,
                     const float* __restrict__ W1,
                     const float* __restrict__ b1,
                     const float* __restrict__ W2,
                     const float* __restrict__ b2,
                     float* __restrict__ out,
                     int E)
{
    extern __shared__ float sm[];
    float* feat_s  = sm;                    // 256*TE floats, layout [k][e]
    float* W1_s    = sm + 256*TE;           // 8192 floats, layout [k][j]
    float* gamma_s = W1_s + 8192;           // 256
    float* beta_s  = gamma_s + 256;         // 256
    float* b1_s    = beta_s + 256;          // 32
    float* W2_s    = b1_s + 32;             // 32

    const int tid = threadIdx.x;

    // ---- cooperative parameter staging ----
    for (int i = tid; i < 8192; i += NTHREADS) W1_s[i] = W1[i];
    for (int i = tid; i < 256; i += NTHREADS) { gamma_s[i] = gamma[i]; beta_s[i] = beta[i]; }
    if (tid < 32) { b1_s[tid] = b1[tid]; W2_s[tid] = W2[tid]; }

    // ---- edge index dtype sniff (int64 vs int32) ----
    // JAX without x64 silently stores int32 despite the int64 annotation.
    // If int64 little-endian, the high 32-bit words of the first 8 (nonneg,
    // <1e5) indices are all zero; for int32 data these words are 8 random
    // indices, essentially never all zero.
    const int* ep32 = (const int*)ep_raw;
    const long long* ep64 = (const long long*)ep_raw;
    int hiOr = 0;
    #pragma unroll
    for (int t = 1; t < 16; t += 2) hiOr |= ep32[t];
    const bool wide = (hiOr == 0);

    // RACE FIX (R1): gamma_s/beta_s are read below by ALL threads across the
    // full 0..255 range, but each thread staged only 2 entries. Must barrier.
    __syncthreads();

    // ---- phase 1: gather + stats + LayerNorm -> feat_s ----
    // 2 threads per edge; each handles 32 of the 64 hidden dims.
    const int e_local = tid >> 1;
    const int half    = tid & 1;
    const long long e = (long long)blockIdx.x * TE + e_local;
    const bool valid  = (e < (long long)E);

    float u[32], v[32];
    float s1 = 0.f, s2 = 0.f;
    if (valid) {
        long long src, dst;
        if (wide) { src = ep64[e];            dst = ep64[e + E]; }
        else      { src = (long long)ep32[e]; dst = (long long)ep32[e + E]; }
        const float4* up = (const float4*)(h + src * 64) + half * 8;
        const float4* vp = (const float4*)(h + dst * 64) + half * 8;
        #pragma unroll
        for (int j = 0; j < 8; j++) {
            float4 a = up[j];
            float4 b = vp[j];
            u[4*j+0]=a.x; u[4*j+1]=a.y; u[4*j+2]=a.z; u[4*j+3]=a.w;
            v[4*j+0]=b.x; v[4*j+1]=b.y; v[4*j+2]=b.z; v[4*j+3]=b.w;
        }
        #pragma unroll
        for (int i = 0; i < 32; i++) {
            float a = u[i], b = v[i];
            float d = fabsf(a - b);
            float p = a * b;
            s1 += ((a + b) + (d + p));
            s2 = fmaf(a, a, s2); s2 = fmaf(b, b, s2);
            s2 = fmaf(d, d, s2); s2 = fmaf(p, p, s2);
        }
    }
    // pair reduce (partner thread of the same edge is the adjacent lane)
    s1 += __shfl_xor_sync(0xffffffffu, s1, 1);
    s2 += __shfl_xor_sync(0xffffffffu, s2, 1);
    const float mu  = s1 * (1.0f/256.0f);
    const float var = fmaf(-mu, mu, s2 * (1.0f/256.0f));
    const float rs  = rsqrtf(var + 1e-5f);

    const int kb = half * 32;
    if (valid) {
        #pragma unroll
        for (int i = 0; i < 32; i++) {
            float a = u[i], v_ = v[i];
            float d = fabsf(a - v_);
            float p = a * v_;
            const int k0 = kb + i;
            float vals[4] = {a, v_, d, p};
            #pragma unroll
            for (int s = 0; s < 4; s++) {
                const int k = s * 64 + k0;
                const float g = gamma_s[k] * rs;
                feat_s[k * TE + e_local] = fmaf(vals[s] - mu, g, beta_s[k]);
            }
        }
    } else {
        #pragma unroll
        for (int i = 0; i < 32; i++) {
            const int k0 = kb + i;
            #pragma unroll
            for (int s = 0; s < 4; s++)
                feat_s[(s * 64 + k0) * TE + e_local] = 0.f;
        }
    }
    __syncthreads();

    // ---- phase 2: GEMM feat_s[64e x 256k] @ W1_s[256k x 32j] ----
    // Thread tile: 4 edges x 4 cols. cg = tid&7 (8 col groups), eg = tid>>3
    // (16 edge groups). feat read: 4 distinct LDS.128 per warp (broadcast over
    // cg). W read: 8 distinct LDS.128 (broadcast over eg). Conflict-free.
    const int cg = tid & 7;
    const int eg = tid >> 3;

    float acc[4][4];
    #pragma unroll
    for (int a = 0; a < 4; a++)
        #pragma unroll
        for (int b = 0; b < 4; b++) acc[a][b] = 0.f;

    const float* fb = feat_s + eg * 4;
    const float* wb = W1_s + cg * 4;
    #pragma unroll 8
    for (int k = 0; k < 256; k++) {
        const float4 f = *(const float4*)(fb + k * TE);
        const float4 w = *(const float4*)(wb + k * 32);
        acc[0][0] = fmaf(f.x, w.x, acc[0][0]);
        acc[0][1] = fmaf(f.x, w.y, acc[0][1]);
        acc[0][2] = fmaf(f.x, w.z, acc[0][2]);
        acc[0][3] = fmaf(f.x, w.w, acc[0][3]);
        acc[1][0] = fmaf(f.y, w.x, acc[1][0]);
        acc[1][1] = fmaf(f.y, w.y, acc[1][1]);
        acc[1][2] = fmaf(f.y, w.z, acc[1][2]);
        acc[1][3] = fmaf(f.y, w.w, acc[1][3]);
        acc[2][0] = fmaf(f.z, w.x, acc[2][0]);
        acc[2][1] = fmaf(f.z, w.y, acc[2][1]);
        acc[2][2] = fmaf(f.z, w.z, acc[2][2]);
        acc[2][3] = fmaf(f.z, w.w, acc[2][3]);
        acc[3][0] = fmaf(f.w, w.x, acc[3][0]);
        acc[3][1] = fmaf(f.w, w.y, acc[3][1]);
        acc[3][2] = fmaf(f.w, w.z, acc[3][2]);
        acc[3][3] = fmaf(f.w, w.w, acc[3][3]);
    }

    // ---- epilogue: bias + ReLU + dot W2, reduce over 8 col groups ----
    const float b2v = b2[0];
    #pragma unroll
    for (int ee = 0; ee < 4; ee++) {
        float pp = 0.f;
        #pragma unroll
        for (int cc = 0; cc < 4; cc++) {
            const int j = cg * 4 + cc;
            const float hm = fmaxf(acc[ee][cc] + b1_s[j], 0.f);
            pp = fmaf(hm, W2_s[j], pp);
        }
        // reduce over cg: lanes differing in bits 0..2 share the same eg
        pp += __shfl_xor_sync(0xffffffffu, pp, 1);
        pp += __shfl_xor_sync(0xffffffffu, pp, 2);
        pp += __shfl_xor_sync(0xffffffffu, pp, 4);
        if (cg == 0) {
            const long long eo = (long long)blockIdx.x * TE + eg * 4 + ee;
            if (eo < (long long)E) out[eo] = pp + b2v;
        }
    }
}

extern "C" void kernel_launch(void* const* d_in, const int* in_sizes, int n_in,
                              void* d_out, int out_size)
{
    const float* h     = (const float*)d_in[0];
    const void*  ep    = d_in[1];
    const float* gamma = (const float*)d_in[2];
    const float* beta  = (const float*)d_in[3];
    const float* W1    = (const float*)d_in[4];
    const float* b1    = (const float*)d_in[5];
    const float* W2    = (const float*)d_in[6];
    const float* b2    = (const float*)d_in[7];
    float* out = (float*)d_out;
    const int E = out_size;

    const size_t smem_bytes = (size_t)SMEM_FLOATS * sizeof(float); // ~100.6 KB
    cudaFuncSetAttribute(edgehead_kernel,
                         cudaFuncAttributeMaxDynamicSharedMemorySize,
                         (int)smem_bytes);

    const int nTiles = (E + TE - 1) / TE;
    edgehead_kernel<<<nTiles, NTHREADS, smem_bytes>>>(
        h, ep, gamma, beta, W1, b1, W2, b2, out, E);
}

// round 4
// speedup vs baseline: 4.7718x; 4.7718x over previous
#include <cuda_runtime.h>
#include <cuda_bf16.h>
#include <stdint.h>

// EdgeHead via warp-level mma.sync (HMMA bf16, supported on plain sm_103):
// out[e] = relu(LN([u,v,|u-v|,u*v]) @ (gamma.*W1) + bc) @ W2 + b2
// with bc = beta @ W1 + b1 (LN affine folded into weights).
// A fragments built in registers (gather ownership == fragment ownership);
// B = (gamma.*W1)^T staged once per CTA in smem as bf16 hi/lo, swizzled.
// 3-term bf16 split: AH*BH + AL*BH + AH*BL  (error ~1e-5).

#define NTHREADS 128

__device__ __forceinline__ uint32_t pack_bf2(float x, float y) {
    __nv_bfloat162 t = __floats2bfloat162_rn(x, y);   // .x = low half
    uint32_t r; memcpy(&r, &t, 4); return r;
}

__device__ __forceinline__ void mma16816(float* c, const uint32_t* a,
                                         uint32_t b0, uint32_t b1) {
    asm volatile(
        "mma.sync.aligned.m16n8k16.row.col.f32.bf16.bf16.f32 "
        "{%0,%1,%2,%3}, {%4,%5,%6,%7}, {%8,%9}, {%0,%1,%2,%3};"
        : "+f"(c[0]), "+f"(c[1]), "+f"(c[2]), "+f"(c[3])
        : "r"(a[0]), "r"(a[1]), "r"(a[2]), "r"(a[3]), "r"(b0), "r"(b1));
}

__device__ __forceinline__ void ldsm4(uint32_t addr, uint32_t& r0, uint32_t& r1,
                                      uint32_t& r2, uint32_t& r3) {
    asm volatile("ldmatrix.sync.aligned.m8n8.x4.shared.b16 {%0,%1,%2,%3}, [%4];"
                 : "=r"(r0), "=r"(r1), "=r"(r2), "=r"(r3) : "r"(addr));
}

// z value for feature segment s from raw u,v pair (compile-time s)
__device__ __forceinline__ float2 zval(int s, float2 uu, float2 vv,
                                       float rs, float nmurs) {
    float2 z;
    if (s == 0)      { z.x = fmaf(uu.x, rs, nmurs); z.y = fmaf(uu.y, rs, nmurs); }
    else if (s == 1) { z.x = fmaf(vv.x, rs, nmurs); z.y = fmaf(vv.y, rs, nmurs); }
    else if (s == 2) { z.x = fmaf(fabsf(uu.x - vv.x), rs, nmurs);
                       z.y = fmaf(fabsf(uu.y - vv.y), rs, nmurs); }
    else             { z.x = fmaf(uu.x * vv.x, rs, nmurs);
                       z.y = fmaf(uu.y * vv.y, rs, nmurs); }
    return z;
}

__global__ __launch_bounds__(NTHREADS, 3)
void edgehead_mma(const float* __restrict__ h,
                  const void* __restrict__ ep_raw,
                  const float* __restrict__ gamma,
                  const float* __restrict__ beta,
                  const float* __restrict__ W1,
                  const float* __restrict__ b1,
                  const float* __restrict__ W2,
                  const float* __restrict__ b2,
                  float* __restrict__ out,
                  int E, int nGroups)
{
    __shared__ __align__(128) unsigned char Bhi[16384];  // 32j x 256k bf16, swz
    __shared__ __align__(128) unsigned char Blo[16384];
    __shared__ float bc_s[32], w2_s[32];

    const int tid = threadIdx.x;
    const int wid = tid >> 5;
    const int lane = tid & 31;

    // ---- stage B^T = (gamma .* W1)^T  bf16 hi/lo, XOR-swizzled ----
    // row j (0..31), 512 B/row; chunk = k>>3 (16B); swz: chunk ^= (j&7)
    for (int p = tid; p < 4096; p += NTHREADS) {
        const int j = p & 31;
        const int k0 = (p >> 5) << 1;
        const float w0 = gamma[k0] * W1[k0 * 32 + j];
        const float w1 = gamma[k0 + 1] * W1[(k0 + 1) * 32 + j];
        const uint32_t off = (uint32_t)(j * 512 + ((((k0 >> 3)) ^ (j & 7)) << 4)
                                        + (k0 & 7) * 2);
        const uint32_t hi = pack_bf2(w0, w1);
        *(uint32_t*)(Bhi + off) = hi;
        const float h0 = __uint_as_float(hi << 16);
        const float h1 = __uint_as_float(hi & 0xffff0000u);
        *(uint32_t*)(Blo + off) = pack_bf2(w0 - h0, w1 - h1);
    }
    if (tid < 32) {
        float acc = b1[tid];
        #pragma unroll 8
        for (int k = 0; k < 256; k++) acc = fmaf(beta[k], W1[k * 32 + tid], acc);
        bc_s[tid] = acc;
        w2_s[tid] = W2[tid];
    }
    __syncthreads();

    // ---- edge index dtype sniff (int64 vs int32) ----
    const int* ep32 = (const int*)ep_raw;
    const long long* ep64 = (const long long*)ep_raw;
    int hiOr = 0;
    #pragma unroll
    for (int t = 1; t < 16; t += 2) hiOr |= ep32[t];
    const bool wide = (hiOr == 0);
    const float b2v = b2[0];

    // ---- per-lane constants ----
    const int c = (lane & 3) * 2;      // k-pair base within 16
    const int q = lane >> 2;           // edge row within group (and +8)

    // bc/w2 fragment preload: per lane, cols j = nt*8 + c (+1)
    float2 bcp[4], w2p[4];
    #pragma unroll
    for (int nt = 0; nt < 4; nt++) {
        bcp[nt].x = bc_s[nt * 8 + c];     bcp[nt].y = bc_s[nt * 8 + c + 1];
        w2p[nt].x = w2_s[nt * 8 + c];     w2p[nt].y = w2_s[nt * 8 + c + 1];
    }

    // ldmatrix lane addressing: x4 = matrices (n0,k0)(n0,k1)(n1,k0)(n1,k1)
    const int x7 = lane & 7;
    const int pday = (lane >> 3) & 1;              // chunk parity this lane serves
    const int jrow = ((lane >> 4)) * 8 + x7;       // j for nbase=0
    const uint32_t bhiB = (uint32_t)__cvta_generic_to_shared(Bhi) + jrow * 512;
    const uint32_t bloB = (uint32_t)__cvta_generic_to_shared(Blo) + jrow * 512;

    const int gw = blockIdx.x * (NTHREADS / 32) + wid;
    const int gstride = gridDim.x * (NTHREADS / 32);

    for (int g = gw; g < nGroups; g += gstride) {
        const long long e0 = (long long)g * 16 + q;
        const long long e1 = e0 + 8;
        const bool v0 = e0 < (long long)E, v1 = e1 < (long long)E;
        long long s0, d0, s1, d1;
        if (wide) {
            s0 = v0 ? ep64[e0] : 0; d0 = v0 ? ep64[e0 + E] : 0;
            s1 = v1 ? ep64[e1] : 0; d1 = v1 ? ep64[e1 + E] : 0;
        } else {
            s0 = v0 ? ep32[e0] : 0; d0 = v0 ? ep32[e0 + E] : 0;
            s1 = v1 ? ep32[e1] : 0; d1 = v1 ? ep32[e1 + E] : 0;
        }

        // gather: lane's dims d = 16t + c (+1) and 16t + 8 + c (+1)
        float2 u0a[4], u0b[4], v0a[4], v0b[4];
        float2 u1a[4], u1b[4], v1a[4], v1b[4];
        {
            const float* pu0 = h + s0 * 64 + c;
            const float* pv0 = h + d0 * 64 + c;
            const float* pu1 = h + s1 * 64 + c;
            const float* pv1 = h + d1 * 64 + c;
            #pragma unroll
            for (int t = 0; t < 4; t++) {
                u0a[t] = *(const float2*)(pu0 + 16 * t);
                u0b[t] = *(const float2*)(pu0 + 16 * t + 8);
                v0a[t] = *(const float2*)(pv0 + 16 * t);
                v0b[t] = *(const float2*)(pv0 + 16 * t + 8);
                u1a[t] = *(const float2*)(pu1 + 16 * t);
                u1b[t] = *(const float2*)(pu1 + 16 * t + 8);
                v1a[t] = *(const float2*)(pv1 + 16 * t);
                v1b[t] = *(const float2*)(pv1 + 16 * t + 8);
            }
        }

        // LN stats per row (quad reduce: lanes 4q..4q+3 share an edge)
        float s1r0 = 0.f, s2r0 = 0.f, s1r1 = 0.f, s2r1 = 0.f;
        #pragma unroll
        for (int t = 0; t < 4; t++) {
            #pragma unroll
            for (int w = 0; w < 4; w++) {
                float uu, vv;
                if (w == 0)      { uu = u0a[t].x; vv = v0a[t].x; }
                else if (w == 1) { uu = u0a[t].y; vv = v0a[t].y; }
                else if (w == 2) { uu = u0b[t].x; vv = v0b[t].x; }
                else             { uu = u0b[t].y; vv = v0b[t].y; }
                const float dd = fabsf(uu - vv), pp = uu * vv;
                s1r0 += (uu + vv) + (dd + pp);
                s2r0 = fmaf(uu, uu, s2r0); s2r0 = fmaf(vv, vv, s2r0);
                s2r0 = fmaf(dd, dd, s2r0); s2r0 = fmaf(pp, pp, s2r0);
                if (w == 0)      { uu = u1a[t].x; vv = v1a[t].x; }
                else if (w == 1) { uu = u1a[t].y; vv = v1a[t].y; }
                else if (w == 2) { uu = u1b[t].x; vv = v1b[t].x; }
                else             { uu = u1b[t].y; vv = v1b[t].y; }
                const float d2 = fabsf(uu - vv), p2 = uu * vv;
                s1r1 += (uu + vv) + (d2 + p2);
                s2r1 = fmaf(uu, uu, s2r1); s2r1 = fmaf(vv, vv, s2r1);
                s2r1 = fmaf(d2, d2, s2r1); s2r1 = fmaf(p2, p2, s2r1);
            }
        }
        s1r0 += __shfl_xor_sync(0xffffffffu, s1r0, 1);
        s1r0 += __shfl_xor_sync(0xffffffffu, s1r0, 2);
        s2r0 += __shfl_xor_sync(0xffffffffu, s2r0, 1);
        s2r0 += __shfl_xor_sync(0xffffffffu, s2r0, 2);
        s1r1 += __shfl_xor_sync(0xffffffffu, s1r1, 1);
        s1r1 += __shfl_xor_sync(0xffffffffu, s1r1, 2);
        s2r1 += __shfl_xor_sync(0xffffffffu, s2r1, 1);
        s2r1 += __shfl_xor_sync(0xffffffffu, s2r1, 2);

        const float mu0 = s1r0 * (1.f / 256.f);
        const float rs0 = rsqrtf(fmaf(-mu0, mu0, s2r0 * (1.f / 256.f)) + 1e-5f);
        const float nm0 = -mu0 * rs0;
        const float mu1 = s1r1 * (1.f / 256.f);
        const float rs1 = rsqrtf(fmaf(-mu1, mu1, s2r1 * (1.f / 256.f)) + 1e-5f);
        const float nm1 = -mu1 * rs1;

        float acc[4][4];
        #pragma unroll
        for (int nt = 0; nt < 4; nt++)
            #pragma unroll
            for (int r = 0; r < 4; r++) acc[nt][r] = 0.f;

        // ---- 16 ksteps: build A frags in regs, ldmatrix B, 12 mma ----
        #pragma unroll
        for (int ks = 0; ks < 16; ks++) {
            const int s = ks >> 2, t = ks & 3;
            const float2 za = zval(s, u0a[t], v0a[t], rs0, nm0);  // r0, k low
            const float2 zb = zval(s, u0b[t], v0b[t], rs0, nm0);  // r0, k high
            const float2 zc = zval(s, u1a[t], v1a[t], rs1, nm1);  // r1, k low
            const float2 zd = zval(s, u1b[t], v1b[t], rs1, nm1);  // r1, k high

            uint32_t ah[4], al[4];
            ah[0] = pack_bf2(za.x, za.y);
            ah[1] = pack_bf2(zc.x, zc.y);
            ah[2] = pack_bf2(zb.x, zb.y);
            ah[3] = pack_bf2(zd.x, zd.y);
            {
                float rx, ry;
                rx = za.x - __uint_as_float(ah[0] << 16);
                ry = za.y - __uint_as_float(ah[0] & 0xffff0000u);
                al[0] = pack_bf2(rx, ry);
                rx = zc.x - __uint_as_float(ah[1] << 16);
                ry = zc.y - __uint_as_float(ah[1] & 0xffff0000u);
                al[1] = pack_bf2(rx, ry);
                rx = zb.x - __uint_as_float(ah[2] << 16);
                ry = zb.y - __uint_as_float(ah[2] & 0xffff0000u);
                al[2] = pack_bf2(rx, ry);
                rx = zd.x - __uint_as_float(ah[3] << 16);
                ry = zd.y - __uint_as_float(ah[3] & 0xffff0000u);
                al[3] = pack_bf2(rx, ry);
            }

            const uint32_t sw = (uint32_t)((((ks * 2 + pday) ^ x7)) << 4);
            uint32_t bh[8], bl[8];
            ldsm4(bhiB + sw,        bh[0], bh[1], bh[2], bh[3]);   // nt 0,1
            ldsm4(bhiB + sw + 8192, bh[4], bh[5], bh[6], bh[7]);   // nt 2,3
            ldsm4(bloB + sw,        bl[0], bl[1], bl[2], bl[3]);
            ldsm4(bloB + sw + 8192, bl[4], bl[5], bl[6], bl[7]);

            #pragma unroll
            for (int nt = 0; nt < 4; nt++) {
                mma16816(acc[nt], ah, bh[2 * nt], bh[2 * nt + 1]);
                mma16816(acc[nt], al, bh[2 * nt], bh[2 * nt + 1]);
                mma16816(acc[nt], ah, bl[2 * nt], bl[2 * nt + 1]);
            }
        }

        // ---- epilogue: relu + W2 dot, quad reduce, store ----
        float pp0 = 0.f, pp1 = 0.f;
        #pragma unroll
        for (int nt = 0; nt < 4; nt++) {
            pp0 = fmaf(fmaxf(acc[nt][0] + bcp[nt].x, 0.f), w2p[nt].x, pp0);
            pp0 = fmaf(fmaxf(acc[nt][1] + bcp[nt].y, 0.f), w2p[nt].y, pp0);
            pp1 = fmaf(fmaxf(acc[nt][2] + bcp[nt].x, 0.f), w2p[nt].x, pp1);
            pp1 = fmaf(fmaxf(acc[nt][3] + bcp[nt].y, 0.f), w2p[nt].y, pp1);
        }
        pp0 += __shfl_xor_sync(0xffffffffu, pp0, 1);
        pp0 += __shfl_xor_sync(0xffffffffu, pp0, 2);
        pp1 += __shfl_xor_sync(0xffffffffu, pp1, 1);
        pp1 += __shfl_xor_sync(0xffffffffu, pp1, 2);
        if ((lane & 3) == 0) {
            if (v0) out[e0] = pp0 + b2v;
            if (v1) out[e1] = pp1 + b2v;
        }
    }
}

extern "C" void kernel_launch(void* const* d_in, const int* in_sizes, int n_in,
                              void* d_out, int out_size)
{
    const float* h     = (const float*)d_in[0];
    const void*  ep    = d_in[1];
    const float* gamma = (const float*)d_in[2];
    const float* beta  = (const float*)d_in[3];
    const float* W1    = (const float*)d_in[4];
    const float* b1    = (const float*)d_in[5];
    const float* W2    = (const float*)d_in[6];
    const float* b2    = (const float*)d_in[7];
    float* out = (float*)d_out;
    const int E = out_size;
    const int nGroups = (E + 15) / 16;

    int dev = 0, sms = 148;
    cudaGetDevice(&dev);
    cudaDeviceGetAttribute(&sms, cudaDevAttrMultiProcessorCount, dev);
    int grid = sms * 3;
    const int maxg = (nGroups + (NTHREADS / 32) - 1) / (NTHREADS / 32);
    if (grid > maxg) grid = maxg;

    edgehead_mma<<<grid, NTHREADS>>>(h, ep, gamma, beta, W1, b1, W2, b2,
                                     out, E, nGroups);
}

// round 5
// speedup vs baseline: 5.4734x; 1.1470x over previous
#include <cuda_runtime.h>
#include <cuda_fp16.h>
#include <stdint.h>

// EdgeHead via warp-level mma.sync (HMMA fp16, plain sm_103-compatible):
// out[e] = relu(LN([u,v,|u-v|,u*v]) @ (gamma.*W1) + bc) @ W2 + b2,
// bc = beta @ W1 + b1 (LN affine folded into weights).
// A fragments built in registers (gather ownership == fragment ownership);
// B = (gamma.*W1)^T staged once per CTA in smem as fp16 (single precision
// term), XOR-swizzled for conflict-free ldmatrix.
// 2-term fp16 split: AH*B + AL*B. Remaining error = B fp16 rounding ~1e-4.

#define NTHREADS 128

__device__ __forceinline__ uint32_t pack_h2(float x, float y) {
    __half2 t = __floats2half2_rn(x, y);   // .x = low half
    uint32_t r; memcpy(&r, &t, 4); return r;
}

__device__ __forceinline__ void mma16816(float* c, const uint32_t* a,
                                         uint32_t b0, uint32_t b1) {
    asm volatile(
        "mma.sync.aligned.m16n8k16.row.col.f32.f16.f16.f32 "
        "{%0,%1,%2,%3}, {%4,%5,%6,%7}, {%8,%9}, {%0,%1,%2,%3};"
        : "+f"(c[0]), "+f"(c[1]), "+f"(c[2]), "+f"(c[3])
        : "r"(a[0]), "r"(a[1]), "r"(a[2]), "r"(a[3]), "r"(b0), "r"(b1));
}

__device__ __forceinline__ void ldsm4(uint32_t addr, uint32_t& r0, uint32_t& r1,
                                      uint32_t& r2, uint32_t& r3) {
    asm volatile("ldmatrix.sync.aligned.m8n8.x4.shared.b16 {%0,%1,%2,%3}, [%4];"
                 : "=r"(r0), "=r"(r1), "=r"(r2), "=r"(r3) : "r"(addr));
}

// z value for feature segment s from raw u,v pair (compile-time s)
__device__ __forceinline__ float2 zval(int s, float2 uu, float2 vv,
                                       float rs, float nmurs) {
    float2 z;
    if (s == 0)      { z.x = fmaf(uu.x, rs, nmurs); z.y = fmaf(uu.y, rs, nmurs); }
    else if (s == 1) { z.x = fmaf(vv.x, rs, nmurs); z.y = fmaf(vv.y, rs, nmurs); }
    else if (s == 2) { z.x = fmaf(fabsf(uu.x - vv.x), rs, nmurs);
                       z.y = fmaf(fabsf(uu.y - vv.y), rs, nmurs); }
    else             { z.x = fmaf(uu.x * vv.x, rs, nmurs);
                       z.y = fmaf(uu.y * vv.y, rs, nmurs); }
    return z;
}

__global__ __launch_bounds__(NTHREADS, 3)
void edgehead_mma(const float* __restrict__ h,
                  const void* __restrict__ ep_raw,
                  const float* __restrict__ gamma,
                  const float* __restrict__ beta,
                  const float* __restrict__ W1,
                  const float* __restrict__ b1,
                  const float* __restrict__ W2,
                  const float* __restrict__ b2,
                  float* __restrict__ out,
                  int E, int nGroups)
{
    __shared__ __align__(128) unsigned char Bhi[16384];  // 32j x 256k fp16, swz
    __shared__ float bc_s[32], w2_s[32];

    const int tid = threadIdx.x;
    const int wid = tid >> 5;
    const int lane = tid & 31;

    // ---- stage B^T = (gamma .* W1)^T  fp16, XOR-swizzled ----
    // row j (0..31), 512 B/row; chunk = k>>3 (16B); swz: chunk ^= (j&7)
    for (int p = tid; p < 4096; p += NTHREADS) {
        const int j = p & 31;
        const int k0 = (p >> 5) << 1;
        const float w0 = gamma[k0] * W1[k0 * 32 + j];
        const float w1 = gamma[k0 + 1] * W1[(k0 + 1) * 32 + j];
        const uint32_t off = (uint32_t)(j * 512 + ((((k0 >> 3)) ^ (j & 7)) << 4)
                                        + (k0 & 7) * 2);
        *(uint32_t*)(Bhi + off) = pack_h2(w0, w1);
    }
    if (tid < 32) {
        float acc = b1[tid];
        #pragma unroll 8
        for (int k = 0; k < 256; k++) acc = fmaf(beta[k], W1[k * 32 + tid], acc);
        bc_s[tid] = acc;
        w2_s[tid] = W2[tid];
    }
    __syncthreads();

    // ---- edge index dtype sniff (int64 vs int32) ----
    const int* ep32 = (const int*)ep_raw;
    const long long* ep64 = (const long long*)ep_raw;
    int hiOr = 0;
    #pragma unroll
    for (int t = 1; t < 16; t += 2) hiOr |= ep32[t];
    const bool wide = (hiOr == 0);
    const float b2v = b2[0];

    // ---- per-lane constants ----
    const int c = (lane & 3) * 2;      // k-pair base within 16
    const int q = lane >> 2;           // edge row within group (and +8)

    // bc/w2 fragment preload: per lane, cols j = nt*8 + c (+1)
    float2 bcp[4], w2p[4];
    #pragma unroll
    for (int nt = 0; nt < 4; nt++) {
        bcp[nt].x = bc_s[nt * 8 + c];     bcp[nt].y = bc_s[nt * 8 + c + 1];
        w2p[nt].x = w2_s[nt * 8 + c];     w2p[nt].y = w2_s[nt * 8 + c + 1];
    }

    // ldmatrix lane addressing: x4 = matrices (n0,k0)(n0,k1)(n1,k0)(n1,k1)
    const int x7 = lane & 7;
    const int pday = (lane >> 3) & 1;              // chunk parity this lane serves
    const int jrow = ((lane >> 4)) * 8 + x7;       // j for nbase=0
    const uint32_t bhiB = (uint32_t)__cvta_generic_to_shared(Bhi) + jrow * 512;

    const int gw = blockIdx.x * (NTHREADS / 32) + wid;
    const int gstride = gridDim.x * (NTHREADS / 32);

    for (int g = gw; g < nGroups; g += gstride) {
        const long long e0 = (long long)g * 16 + q;
        const long long e1 = e0 + 8;
        const bool v0 = e0 < (long long)E, v1 = e1 < (long long)E;
        long long s0, d0, s1, d1;
        if (wide) {
            s0 = v0 ? ep64[e0] : 0; d0 = v0 ? ep64[e0 + E] : 0;
            s1 = v1 ? ep64[e1] : 0; d1 = v1 ? ep64[e1 + E] : 0;
        } else {
            s0 = v0 ? ep32[e0] : 0; d0 = v0 ? ep32[e0 + E] : 0;
            s1 = v1 ? ep32[e1] : 0; d1 = v1 ? ep32[e1 + E] : 0;
        }

        // gather: lane's dims d = 16t + c (+1) and 16t + 8 + c (+1)
        float2 u0a[4], u0b[4], v0a[4], v0b[4];
        float2 u1a[4], u1b[4], v1a[4], v1b[4];
        {
            const float* pu0 = h + s0 * 64 + c;
            const float* pv0 = h + d0 * 64 + c;
            const float* pu1 = h + s1 * 64 + c;
            const float* pv1 = h + d1 * 64 + c;
            #pragma unroll
            for (int t = 0; t < 4; t++) {
                u0a[t] = *(const float2*)(pu0 + 16 * t);
                u0b[t] = *(const float2*)(pu0 + 16 * t + 8);
                v0a[t] = *(const float2*)(pv0 + 16 * t);
                v0b[t] = *(const float2*)(pv0 + 16 * t + 8);
                u1a[t] = *(const float2*)(pu1 + 16 * t);
                u1b[t] = *(const float2*)(pu1 + 16 * t + 8);
                v1a[t] = *(const float2*)(pv1 + 16 * t);
                v1b[t] = *(const float2*)(pv1 + 16 * t + 8);
            }
        }

        // LN stats per row (quad reduce: lanes 4q..4q+3 share an edge)
        float s1r0 = 0.f, s2r0 = 0.f, s1r1 = 0.f, s2r1 = 0.f;
        #pragma unroll
        for (int t = 0; t < 4; t++) {
            #pragma unroll
            for (int w = 0; w < 4; w++) {
                float uu, vv;
                if (w == 0)      { uu = u0a[t].x; vv = v0a[t].x; }
                else if (w == 1) { uu = u0a[t].y; vv = v0a[t].y; }
                else if (w == 2) { uu = u0b[t].x; vv = v0b[t].x; }
                else             { uu = u0b[t].y; vv = v0b[t].y; }
                const float dd = fabsf(uu - vv), pp = uu * vv;
                s1r0 += (uu + vv) + (dd + pp);
                s2r0 = fmaf(uu, uu, s2r0); s2r0 = fmaf(vv, vv, s2r0);
                s2r0 = fmaf(dd, dd, s2r0); s2r0 = fmaf(pp, pp, s2r0);
                if (w == 0)      { uu = u1a[t].x; vv = v1a[t].x; }
                else if (w == 1) { uu = u1a[t].y; vv = v1a[t].y; }
                else if (w == 2) { uu = u1b[t].x; vv = v1b[t].x; }
                else             { uu = u1b[t].y; vv = v1b[t].y; }
                const float d2 = fabsf(uu - vv), p2 = uu * vv;
                s1r1 += (uu + vv) + (d2 + p2);
                s2r1 = fmaf(uu, uu, s2r1); s2r1 = fmaf(vv, vv, s2r1);
                s2r1 = fmaf(d2, d2, s2r1); s2r1 = fmaf(p2, p2, s2r1);
            }
        }
        s1r0 += __shfl_xor_sync(0xffffffffu, s1r0, 1);
        s1r0 += __shfl_xor_sync(0xffffffffu, s1r0, 2);
        s2r0 += __shfl_xor_sync(0xffffffffu, s2r0, 1);
        s2r0 += __shfl_xor_sync(0xffffffffu, s2r0, 2);
        s1r1 += __shfl_xor_sync(0xffffffffu, s1r1, 1);
        s1r1 += __shfl_xor_sync(0xffffffffu, s1r1, 2);
        s2r1 += __shfl_xor_sync(0xffffffffu, s2r1, 1);
        s2r1 += __shfl_xor_sync(0xffffffffu, s2r1, 2);

        const float mu0 = s1r0 * (1.f / 256.f);
        const float rs0 = rsqrtf(fmaf(-mu0, mu0, s2r0 * (1.f / 256.f)) + 1e-5f);
        const float nm0 = -mu0 * rs0;
        const float mu1 = s1r1 * (1.f / 256.f);
        const float rs1 = rsqrtf(fmaf(-mu1, mu1, s2r1 * (1.f / 256.f)) + 1e-5f);
        const float nm1 = -mu1 * rs1;

        float acc[4][4];
        #pragma unroll
        for (int nt = 0; nt < 4; nt++)
            #pragma unroll
            for (int r = 0; r < 4; r++) acc[nt][r] = 0.f;

        // ---- 16 ksteps: build A frags in regs, ldmatrix B, 8 mma ----
        #pragma unroll
        for (int ks = 0; ks < 16; ks++) {
            const int s = ks >> 2, t = ks & 3;
            const float2 za = zval(s, u0a[t], v0a[t], rs0, nm0);  // r0, k low
            const float2 zb = zval(s, u0b[t], v0b[t], rs0, nm0);  // r0, k high
            const float2 zc = zval(s, u1a[t], v1a[t], rs1, nm1);  // r1, k low
            const float2 zd = zval(s, u1b[t], v1b[t], rs1, nm1);  // r1, k high

            uint32_t ah[4], al[4];
            ah[0] = pack_h2(za.x, za.y);
            ah[1] = pack_h2(zc.x, zc.y);
            ah[2] = pack_h2(zb.x, zb.y);
            ah[3] = pack_h2(zd.x, zd.y);
            {
                __half2 t0 = *reinterpret_cast<__half2*>(&ah[0]);
                al[0] = pack_h2(za.x - __low2float(t0), za.y - __high2float(t0));
                __half2 t1 = *reinterpret_cast<__half2*>(&ah[1]);
                al[1] = pack_h2(zc.x - __low2float(t1), zc.y - __high2float(t1));
                __half2 t2 = *reinterpret_cast<__half2*>(&ah[2]);
                al[2] = pack_h2(zb.x - __low2float(t2), zb.y - __high2float(t2));
                __half2 t3 = *reinterpret_cast<__half2*>(&ah[3]);
                al[3] = pack_h2(zd.x - __low2float(t3), zd.y - __high2float(t3));
            }

            const uint32_t sw = (uint32_t)((((ks * 2 + pday) ^ x7)) << 4);
            uint32_t bh[8];
            ldsm4(bhiB + sw,        bh[0], bh[1], bh[2], bh[3]);   // nt 0,1
            ldsm4(bhiB + sw + 8192, bh[4], bh[5], bh[6], bh[7]);   // nt 2,3

            #pragma unroll
            for (int nt = 0; nt < 4; nt++) {
                mma16816(acc[nt], ah, bh[2 * nt], bh[2 * nt + 1]);
                mma16816(acc[nt], al, bh[2 * nt], bh[2 * nt + 1]);
            }
        }

        // ---- epilogue: relu + W2 dot, quad reduce, store ----
        float pp0 = 0.f, pp1 = 0.f;
        #pragma unroll
        for (int nt = 0; nt < 4; nt++) {
            pp0 = fmaf(fmaxf(acc[nt][0] + bcp[nt].x, 0.f), w2p[nt].x, pp0);
            pp0 = fmaf(fmaxf(acc[nt][1] + bcp[nt].y, 0.f), w2p[nt].y, pp0);
            pp1 = fmaf(fmaxf(acc[nt][2] + bcp[nt].x, 0.f), w2p[nt].x, pp1);
            pp1 = fmaf(fmaxf(acc[nt][3] + bcp[nt].y, 0.f), w2p[nt].y, pp1);
        }
        pp0 += __shfl_xor_sync(0xffffffffu, pp0, 1);
        pp0 += __shfl_xor_sync(0xffffffffu, pp0, 2);
        pp1 += __shfl_xor_sync(0xffffffffu, pp1, 1);
        pp1 += __shfl_xor_sync(0xffffffffu, pp1, 2);
        if ((lane & 3) == 0) {
            if (v0) out[e0] = pp0 + b2v;
            if (v1) out[e1] = pp1 + b2v;
        }
    }
}

extern "C" void kernel_launch(void* const* d_in, const int* in_sizes, int n_in,
                              void* d_out, int out_size)
{
    const float* h     = (const float*)d_in[0];
    const void*  ep    = d_in[1];
    const float* gamma = (const float*)d_in[2];
    const float* beta  = (const float*)d_in[3];
    const float* W1    = (const float*)d_in[4];
    const float* b1    = (const float*)d_in[5];
    const float* W2    = (const float*)d_in[6];
    const float* b2    = (const float*)d_in[7];
    float* out = (float*)d_out;
    const int E = out_size;
    const int nGroups = (E + 15) / 16;

    int dev = 0, sms = 148;
    cudaGetDevice(&dev);
    cudaDeviceGetAttribute(&sms, cudaDevAttrMultiProcessorCount, dev);
    int grid = sms * 3;
    const int maxg = (nGroups + (NTHREADS / 32) - 1) / (NTHREADS / 32);
    if (grid > maxg) grid = maxg;

    edgehead_mma<<<grid, NTHREADS>>>(h, ep, gamma, beta, W1, b1, W2, b2,
                                     out, E, nGroups);
}

// round 6
// speedup vs baseline: 7.1921x; 1.3140x over previous
#include <cuda_runtime.h>
#include <cuda_fp16.h>
#include <stdint.h>

// EdgeHead via warp-level mma.sync (HMMA fp16, plain sm_103-compatible):
// out[e] = relu(LN([u,v,|u-v|,u*v]) @ (gamma.*W1) + bc) @ W2 + b2,
// bc = beta @ W1 + b1 (LN affine folded into weights).
// A fragments built in registers (gather ownership == fragment ownership);
// B = (gamma.*W1)^T staged once per CTA in smem as fp16, XOR-swizzled for
// conflict-free ldmatrix. Both operands single-fp16 (no split): total error
// ~3e-4, threshold 1e-3. fp32 HMMA accumulate.

#define NTHREADS 128

__device__ __forceinline__ uint32_t pack_h2(float x, float y) {
    __half2 t = __floats2half2_rn(x, y);   // .x = low half
    uint32_t r; memcpy(&r, &t, 4); return r;
}

__device__ __forceinline__ void mma16816(float* c, const uint32_t* a,
                                         uint32_t b0, uint32_t b1) {
    asm volatile(
        "mma.sync.aligned.m16n8k16.row.col.f32.f16.f16.f32 "
        "{%0,%1,%2,%3}, {%4,%5,%6,%7}, {%8,%9}, {%0,%1,%2,%3};"
        : "+f"(c[0]), "+f"(c[1]), "+f"(c[2]), "+f"(c[3])
        : "r"(a[0]), "r"(a[1]), "r"(a[2]), "r"(a[3]), "r"(b0), "r"(b1));
}

__device__ __forceinline__ void ldsm4(uint32_t addr, uint32_t& r0, uint32_t& r1,
                                      uint32_t& r2, uint32_t& r3) {
    asm volatile("ldmatrix.sync.aligned.m8n8.x4.shared.b16 {%0,%1,%2,%3}, [%4];"
                 : "=r"(r0), "=r"(r1), "=r"(r2), "=r"(r3) : "r"(addr));
}

// z value for feature segment s from raw u,v pair (compile-time s)
__device__ __forceinline__ float2 zval(int s, float2 uu, float2 vv,
                                       float rs, float nmurs) {
    float2 z;
    if (s == 0)      { z.x = fmaf(uu.x, rs, nmurs); z.y = fmaf(uu.y, rs, nmurs); }
    else if (s == 1) { z.x = fmaf(vv.x, rs, nmurs); z.y = fmaf(vv.y, rs, nmurs); }
    else if (s == 2) { z.x = fmaf(fabsf(uu.x - vv.x), rs, nmurs);
                       z.y = fmaf(fabsf(uu.y - vv.y), rs, nmurs); }
    else             { z.x = fmaf(uu.x * vv.x, rs, nmurs);
                       z.y = fmaf(uu.y * vv.y, rs, nmurs); }
    return z;
}

__global__ __launch_bounds__(NTHREADS, 4)
void edgehead_mma(const float* __restrict__ h,
                  const void* __restrict__ ep_raw,
                  const float* __restrict__ gamma,
                  const float* __restrict__ beta,
                  const float* __restrict__ W1,
                  const float* __restrict__ b1,
                  const float* __restrict__ W2,
                  const float* __restrict__ b2,
                  float* __restrict__ out,
                  int E, int nGroups)
{
    __shared__ __align__(128) unsigned char Bhi[16384];  // 32j x 256k fp16, swz
    __shared__ float bc_s[32], w2_s[32];

    const int tid = threadIdx.x;
    const int wid = tid >> 5;
    const int lane = tid & 31;

    // ---- stage B^T = (gamma .* W1)^T  fp16, XOR-swizzled ----
    // row j (0..31), 512 B/row; chunk = k>>3 (16B); swz: chunk ^= (j&7)
    for (int p = tid; p < 4096; p += NTHREADS) {
        const int j = p & 31;
        const int k0 = (p >> 5) << 1;
        const float w0 = gamma[k0] * W1[k0 * 32 + j];
        const float w1 = gamma[k0 + 1] * W1[(k0 + 1) * 32 + j];
        const uint32_t off = (uint32_t)(j * 512 + ((((k0 >> 3)) ^ (j & 7)) << 4)
                                        + (k0 & 7) * 2);
        *(uint32_t*)(Bhi + off) = pack_h2(w0, w1);
    }
    if (tid < 32) {
        float acc = b1[tid];
        #pragma unroll 8
        for (int k = 0; k < 256; k++) acc = fmaf(beta[k], W1[k * 32 + tid], acc);
        bc_s[tid] = acc;
        w2_s[tid] = W2[tid];
    }
    __syncthreads();

    // ---- edge index dtype sniff (int64 vs int32) ----
    const int* ep32 = (const int*)ep_raw;
    const long long* ep64 = (const long long*)ep_raw;
    int hiOr = 0;
    #pragma unroll
    for (int t = 1; t < 16; t += 2) hiOr |= ep32[t];
    const bool wide = (hiOr == 0);
    const float b2v = b2[0];

    // ---- per-lane constants ----
    const int c = (lane & 3) * 2;      // k-pair base within 16
    const int q = lane >> 2;           // edge row within group (and +8)

    // ldmatrix lane addressing: x4 = matrices (n0,k0)(n0,k1)(n1,k0)(n1,k1)
    const int x7 = lane & 7;
    const int pday = (lane >> 3) & 1;              // chunk parity this lane serves
    const int jrow = ((lane >> 4)) * 8 + x7;       // j for nbase=0
    const uint32_t bhiB = (uint32_t)__cvta_generic_to_shared(Bhi) + jrow * 512;

    const int gw = blockIdx.x * (NTHREADS / 32) + wid;
    const int gstride = gridDim.x * (NTHREADS / 32);

    for (int g = gw; g < nGroups; g += gstride) {
        const long long e0 = (long long)g * 16 + q;
        const long long e1 = e0 + 8;
        const bool v0 = e0 < (long long)E, v1 = e1 < (long long)E;
        long long s0, d0, s1, d1;
        if (wide) {
            s0 = v0 ? ep64[e0] : 0; d0 = v0 ? ep64[e0 + E] : 0;
            s1 = v1 ? ep64[e1] : 0; d1 = v1 ? ep64[e1 + E] : 0;
        } else {
            s0 = v0 ? ep32[e0] : 0; d0 = v0 ? ep32[e0 + E] : 0;
            s1 = v1 ? ep32[e1] : 0; d1 = v1 ? ep32[e1 + E] : 0;
        }

        // gather: lane's dims d = 16t + c (+1) and 16t + 8 + c (+1)
        float2 u0a[4], u0b[4], v0a[4], v0b[4];
        float2 u1a[4], u1b[4], v1a[4], v1b[4];
        {
            const float* pu0 = h + s0 * 64 + c;
            const float* pv0 = h + d0 * 64 + c;
            const float* pu1 = h + s1 * 64 + c;
            const float* pv1 = h + d1 * 64 + c;
            #pragma unroll
            for (int t = 0; t < 4; t++) {
                u0a[t] = *(const float2*)(pu0 + 16 * t);
                u0b[t] = *(const float2*)(pu0 + 16 * t + 8);
                v0a[t] = *(const float2*)(pv0 + 16 * t);
                v0b[t] = *(const float2*)(pv0 + 16 * t + 8);
                u1a[t] = *(const float2*)(pu1 + 16 * t);
                u1b[t] = *(const float2*)(pu1 + 16 * t + 8);
                v1a[t] = *(const float2*)(pv1 + 16 * t);
                v1b[t] = *(const float2*)(pv1 + 16 * t + 8);
            }
        }

        // LN stats per row (quad reduce: lanes 4q..4q+3 share an edge)
        float s1r0 = 0.f, s2r0 = 0.f, s1r1 = 0.f, s2r1 = 0.f;
        #pragma unroll
        for (int t = 0; t < 4; t++) {
            #pragma unroll
            for (int w = 0; w < 4; w++) {
                float uu, vv;
                if (w == 0)      { uu = u0a[t].x; vv = v0a[t].x; }
                else if (w == 1) { uu = u0a[t].y; vv = v0a[t].y; }
                else if (w == 2) { uu = u0b[t].x; vv = v0b[t].x; }
                else             { uu = u0b[t].y; vv = v0b[t].y; }
                const float dd = fabsf(uu - vv), pp = uu * vv;
                s1r0 += (uu + vv) + (dd + pp);
                s2r0 = fmaf(uu, uu, s2r0); s2r0 = fmaf(vv, vv, s2r0);
                s2r0 = fmaf(dd, dd, s2r0); s2r0 = fmaf(pp, pp, s2r0);
                if (w == 0)      { uu = u1a[t].x; vv = v1a[t].x; }
                else if (w == 1) { uu = u1a[t].y; vv = v1a[t].y; }
                else if (w == 2) { uu = u1b[t].x; vv = v1b[t].x; }
                else             { uu = u1b[t].y; vv = v1b[t].y; }
                const float d2 = fabsf(uu - vv), p2 = uu * vv;
                s1r1 += (uu + vv) + (d2 + p2);
                s2r1 = fmaf(uu, uu, s2r1); s2r1 = fmaf(vv, vv, s2r1);
                s2r1 = fmaf(d2, d2, s2r1); s2r1 = fmaf(p2, p2, s2r1);
            }
        }
        s1r0 += __shfl_xor_sync(0xffffffffu, s1r0, 1);
        s1r0 += __shfl_xor_sync(0xffffffffu, s1r0, 2);
        s2r0 += __shfl_xor_sync(0xffffffffu, s2r0, 1);
        s2r0 += __shfl_xor_sync(0xffffffffu, s2r0, 2);
        s1r1 += __shfl_xor_sync(0xffffffffu, s1r1, 1);
        s1r1 += __shfl_xor_sync(0xffffffffu, s1r1, 2);
        s2r1 += __shfl_xor_sync(0xffffffffu, s2r1, 1);
        s2r1 += __shfl_xor_sync(0xffffffffu, s2r1, 2);

        const float mu0 = s1r0 * (1.f / 256.f);
        const float rs0 = rsqrtf(fmaf(-mu0, mu0, s2r0 * (1.f / 256.f)) + 1e-5f);
        const float nm0 = -mu0 * rs0;
        const float mu1 = s1r1 * (1.f / 256.f);
        const float rs1 = rsqrtf(fmaf(-mu1, mu1, s2r1 * (1.f / 256.f)) + 1e-5f);
        const float nm1 = -mu1 * rs1;

        float acc[4][4];
        #pragma unroll
        for (int nt = 0; nt < 4; nt++)
            #pragma unroll
            for (int r = 0; r < 4; r++) acc[nt][r] = 0.f;

        // ---- 16 ksteps: build A frags in regs, ldmatrix B, 4 mma ----
        #pragma unroll
        for (int ks = 0; ks < 16; ks++) {
            const int s = ks >> 2, t = ks & 3;
            const float2 za = zval(s, u0a[t], v0a[t], rs0, nm0);  // r0, k low
            const float2 zb = zval(s, u0b[t], v0b[t], rs0, nm0);  // r0, k high
            const float2 zc = zval(s, u1a[t], v1a[t], rs1, nm1);  // r1, k low
            const float2 zd = zval(s, u1b[t], v1b[t], rs1, nm1);  // r1, k high

            uint32_t ah[4];
            ah[0] = pack_h2(za.x, za.y);
            ah[1] = pack_h2(zc.x, zc.y);
            ah[2] = pack_h2(zb.x, zb.y);
            ah[3] = pack_h2(zd.x, zd.y);

            const uint32_t sw = (uint32_t)((((ks * 2 + pday) ^ x7)) << 4);
            uint32_t bh[8];
            ldsm4(bhiB + sw,        bh[0], bh[1], bh[2], bh[3]);   // nt 0,1
            ldsm4(bhiB + sw + 8192, bh[4], bh[5], bh[6], bh[7]);   // nt 2,3

            #pragma unroll
            for (int nt = 0; nt < 4; nt++)
                mma16816(acc[nt], ah, bh[2 * nt], bh[2 * nt + 1]);
        }

        // ---- epilogue: relu + W2 dot (bc/w2 from smem), quad reduce ----
        float pp0 = 0.f, pp1 = 0.f;
        #pragma unroll
        for (int nt = 0; nt < 4; nt++) {
            const float bcx = bc_s[nt * 8 + c], bcy = bc_s[nt * 8 + c + 1];
            const float w2x = w2_s[nt * 8 + c], w2y = w2_s[nt * 8 + c + 1];
            pp0 = fmaf(fmaxf(acc[nt][0] + bcx, 0.f), w2x, pp0);
            pp0 = fmaf(fmaxf(acc[nt][1] + bcy, 0.f), w2y, pp0);
            pp1 = fmaf(fmaxf(acc[nt][2] + bcx, 0.f), w2x, pp1);
            pp1 = fmaf(fmaxf(acc[nt][3] + bcy, 0.f), w2y, pp1);
        }
        pp0 += __shfl_xor_sync(0xffffffffu, pp0, 1);
        pp0 += __shfl_xor_sync(0xffffffffu, pp0, 2);
        pp1 += __shfl_xor_sync(0xffffffffu, pp1, 1);
        pp1 += __shfl_xor_sync(0xffffffffu, pp1, 2);
        if ((lane & 3) == 0) {
            if (v0) out[e0] = pp0 + b2v;
            if (v1) out[e1] = pp1 + b2v;
        }
    }
}

extern "C" void kernel_launch(void* const* d_in, const int* in_sizes, int n_in,
                              void* d_out, int out_size)
{
    const float* h     = (const float*)d_in[0];
    const void*  ep    = d_in[1];
    const float* gamma = (const float*)d_in[2];
    const float* beta  = (const float*)d_in[3];
    const float* W1    = (const float*)d_in[4];
    const float* b1    = (const float*)d_in[5];
    const float* W2    = (const float*)d_in[6];
    const float* b2    = (const float*)d_in[7];
    float* out = (float*)d_out;
    const int E = out_size;
    const int nGroups = (E + 15) / 16;

    int dev = 0, sms = 148;
    cudaGetDevice(&dev);
    cudaDeviceGetAttribute(&sms, cudaDevAttrMultiProcessorCount, dev);
    int grid = sms * 4;
    const int maxg = (nGroups + (NTHREADS / 32) - 1) / (NTHREADS / 32);
    if (grid > maxg) grid = maxg;

    edgehead_mma<<<grid, NTHREADS>>>(h, ep, gamma, beta, W1, b1, W2, b2,
                                     out, E, nGroups);
}

// round 7
// speedup vs baseline: 8.2707x; 1.1500x over previous
#include <cuda_runtime.h>
#include <cuda_fp16.h>
#include <stdint.h>

// EdgeHead via warp-level mma.sync (HMMA fp16, plain sm_103-compatible):
// out[e] = relu(LN([u,v,|u-v|,u*v]) @ (gamma.*W1) + bc) @ W2 + b2,
// bc = beta @ W1 + b1 (LN affine folded into weights).
// A fragments built in registers; gathers use LDG.128 via a k-axis
// permutation (lane owns 4 contiguous dims; float4.xy -> mma k-lo pair,
// float4.zw -> mma k-hi pair). B stored with the SAME permutation, so the
// GEMM result is unchanged. All addressing 32-bit.

#define NTHREADS 128

__device__ __forceinline__ uint32_t pack_h2(float x, float y) {
    __half2 t = __floats2half2_rn(x, y);   // .x = low half
    uint32_t r; memcpy(&r, &t, 4); return r;
}

__device__ __forceinline__ void mma16816(float* c, const uint32_t* a,
                                         uint32_t b0, uint32_t b1) {
    asm volatile(
        "mma.sync.aligned.m16n8k16.row.col.f32.f16.f16.f32 "
        "{%0,%1,%2,%3}, {%4,%5,%6,%7}, {%8,%9}, {%0,%1,%2,%3};"
        : "+f"(c[0]), "+f"(c[1]), "+f"(c[2]), "+f"(c[3])
        : "r"(a[0]), "r"(a[1]), "r"(a[2]), "r"(a[3]), "r"(b0), "r"(b1));
}

__device__ __forceinline__ void ldsm4(uint32_t addr, uint32_t& r0, uint32_t& r1,
                                      uint32_t& r2, uint32_t& r3) {
    asm volatile("ldmatrix.sync.aligned.m8n8.x4.shared.b16 {%0,%1,%2,%3}, [%4];"
                 : "=r"(r0), "=r"(r1), "=r"(r2), "=r"(r3) : "r"(addr));
}

// z pair for feature segment s from raw (u,v) pairs (compile-time s)
__device__ __forceinline__ float2 zval(int s, float ux, float uy,
                                       float vx, float vy,
                                       float rs, float nmurs) {
    float2 z;
    if (s == 0)      { z.x = fmaf(ux, rs, nmurs); z.y = fmaf(uy, rs, nmurs); }
    else if (s == 1) { z.x = fmaf(vx, rs, nmurs); z.y = fmaf(vy, rs, nmurs); }
    else if (s == 2) { z.x = fmaf(fabsf(ux - vx), rs, nmurs);
                       z.y = fmaf(fabsf(uy - vy), rs, nmurs); }
    else             { z.x = fmaf(ux * vx, rs, nmurs);
                       z.y = fmaf(uy * vy, rs, nmurs); }
    return z;
}

__global__ __launch_bounds__(NTHREADS, 4)
void edgehead_mma(const float* __restrict__ h,
                  const void* __restrict__ ep_raw,
                  const float* __restrict__ gamma,
                  const float* __restrict__ beta,
                  const float* __restrict__ W1,
                  const float* __restrict__ b1,
                  const float* __restrict__ W2,
                  const float* __restrict__ b2,
                  float* __restrict__ out,
                  int E, int nGroups)
{
    __shared__ __align__(128) unsigned char Bhi[16384];  // 32j x 256k fp16, swz
    __shared__ float bc_s[32], w2_s[32];

    const int tid = threadIdx.x;
    const int wid = tid >> 5;
    const int lane = tid & 31;

    // ---- stage B^T = (gamma .* W1)^T fp16, k-permuted + XOR-swizzled ----
    // phys k within 16-block maps to mma col m = ((k&12)>>1) + ((k&2)?8:0);
    // (k even -> k,k+1 land on adjacent m, so pair-writes stay valid)
    // row j (0..31), 512 B/row; chunk = kp>>3 (16B); swz: chunk ^= (j&7)
    for (int p = tid; p < 4096; p += NTHREADS) {
        const int j = p & 31;
        const int k0 = (p >> 5) << 1;                    // even phys k
        const float w0 = gamma[k0] * W1[k0 * 32 + j];
        const float w1 = gamma[k0 + 1] * W1[(k0 + 1) * 32 + j];
        const int m0 = ((k0 & 12) >> 1) + ((k0 & 2) ? 8 : 0);
        const int kp = (k0 & ~15) + m0;                  // permuted, even
        const uint32_t off = (uint32_t)(j * 512 + ((((kp >> 3)) ^ (j & 7)) << 4)
                                        + (kp & 7) * 2);
        *(uint32_t*)(Bhi + off) = pack_h2(w0, w1);
    }
    if (tid < 32) {
        float acc = b1[tid];
        #pragma unroll 8
        for (int k = 0; k < 256; k++) acc = fmaf(beta[k], W1[k * 32 + tid], acc);
        bc_s[tid] = acc;
        w2_s[tid] = W2[tid];
    }
    __syncthreads();

    // ---- edge index dtype sniff (int64 vs int32) ----
    const int* ep32 = (const int*)ep_raw;
    const long long* ep64 = (const long long*)ep_raw;
    int hiOr = 0;
    #pragma unroll
    for (int t = 1; t < 16; t += 2) hiOr |= ep32[t];
    const bool wide = (hiOr == 0);
    const float b2v = b2[0];

    // ---- per-lane constants ----
    const int cq = lane & 3;           // quad position: owns phys dims 4cq..+3
    const int q = lane >> 2;           // edge row within group (and +8)
    const float4* __restrict__ hv4 = (const float4*)h;   // 16 float4 per node

    // ldmatrix lane addressing: x4 = matrices (n0,k0)(n0,k1)(n1,k0)(n1,k1)
    const int x7 = lane & 7;
    const int pday = (lane >> 3) & 1;              // chunk parity this lane serves
    const int jrow = ((lane >> 4)) * 8 + x7;       // j for nbase=0
    const uint32_t bhiB = (uint32_t)__cvta_generic_to_shared(Bhi) + jrow * 512;

    const int gw = blockIdx.x * (NTHREADS / 32) + wid;
    const int gstride = gridDim.x * (NTHREADS / 32);

    for (int g = gw; g < nGroups; g += gstride) {
        const int e0 = g * 16 + q;
        const int e1 = e0 + 8;
        const bool v0 = e0 < E, v1 = e1 < E;
        int s0, d0, s1i, d1;
        if (wide) {
            s0 = v0 ? (int)ep64[e0] : 0; d0 = v0 ? (int)ep64[e0 + E] : 0;
            s1i = v1 ? (int)ep64[e1] : 0; d1 = v1 ? (int)ep64[e1 + E] : 0;
        } else {
            s0 = v0 ? ep32[e0] : 0; d0 = v0 ? ep32[e0 + E] : 0;
            s1i = v1 ? ep32[e1] : 0; d1 = v1 ? ep32[e1 + E] : 0;
        }

        // gather: lane owns phys dims {16t + 4cq .. +3}, one float4 per t
        float4 u0[4], v0r[4], u1[4], v1r[4];
        {
            const float4* pu0 = hv4 + (s0 * 16 + cq);
            const float4* pv0 = hv4 + (d0 * 16 + cq);
            const float4* pu1 = hv4 + (s1i * 16 + cq);
            const float4* pv1 = hv4 + (d1 * 16 + cq);
            #pragma unroll
            for (int t = 0; t < 4; t++) {
                u0[t]  = pu0[4 * t];
                v0r[t] = pv0[4 * t];
                u1[t]  = pu1[4 * t];
                v1r[t] = pv1[4 * t];
            }
        }

        // LN stats per row (quad reduce: lanes 4q..4q+3 share an edge)
        float s1r0 = 0.f, s2r0 = 0.f, s1r1 = 0.f, s2r1 = 0.f;
        #pragma unroll
        for (int t = 0; t < 4; t++) {
            const float* ua = (const float*)&u0[t];
            const float* va = (const float*)&v0r[t];
            const float* ub = (const float*)&u1[t];
            const float* vb = (const float*)&v1r[t];
            #pragma unroll
            for (int w = 0; w < 4; w++) {
                const float uu = ua[w], vv = va[w];
                const float dd = fabsf(uu - vv), pp = uu * vv;
                s1r0 += (uu + vv) + (dd + pp);
                s2r0 = fmaf(uu, uu, s2r0); s2r0 = fmaf(vv, vv, s2r0);
                s2r0 = fmaf(dd, dd, s2r0); s2r0 = fmaf(pp, pp, s2r0);
                const float u2 = ub[w], v2 = vb[w];
                const float d2 = fabsf(u2 - v2), p2 = u2 * v2;
                s1r1 += (u2 + v2) + (d2 + p2);
                s2r1 = fmaf(u2, u2, s2r1); s2r1 = fmaf(v2, v2, s2r1);
                s2r1 = fmaf(d2, d2, s2r1); s2r1 = fmaf(p2, p2, s2r1);
            }
        }
        s1r0 += __shfl_xor_sync(0xffffffffu, s1r0, 1);
        s1r0 += __shfl_xor_sync(0xffffffffu, s1r0, 2);
        s2r0 += __shfl_xor_sync(0xffffffffu, s2r0, 1);
        s2r0 += __shfl_xor_sync(0xffffffffu, s2r0, 2);
        s1r1 += __shfl_xor_sync(0xffffffffu, s1r1, 1);
        s1r1 += __shfl_xor_sync(0xffffffffu, s1r1, 2);
        s2r1 += __shfl_xor_sync(0xffffffffu, s2r1, 1);
        s2r1 += __shfl_xor_sync(0xffffffffu, s2r1, 2);

        const float mu0 = s1r0 * (1.f / 256.f);
        const float rs0 = rsqrtf(fmaf(-mu0, mu0, s2r0 * (1.f / 256.f)) + 1e-5f);
        const float nm0 = -mu0 * rs0;
        const float mu1 = s1r1 * (1.f / 256.f);
        const float rs1 = rsqrtf(fmaf(-mu1, mu1, s2r1 * (1.f / 256.f)) + 1e-5f);
        const float nm1 = -mu1 * rs1;

        float acc[4][4];
        #pragma unroll
        for (int nt = 0; nt < 4; nt++)
            #pragma unroll
            for (int r = 0; r < 4; r++) acc[nt][r] = 0.f;

        // ---- 16 ksteps: A frags from float4 halves, ldmatrix B, 4 mma ----
        // float4.xy -> mma k-lo pair (cols 2cq,2cq+1); .zw -> k-hi (cols +8)
        #pragma unroll
        for (int ks = 0; ks < 16; ks++) {
            const int s = ks >> 2, t = ks & 3;
            const float2 za = zval(s, u0[t].x, u0[t].y, v0r[t].x, v0r[t].y, rs0, nm0);
            const float2 zb = zval(s, u0[t].z, u0[t].w, v0r[t].z, v0r[t].w, rs0, nm0);
            const float2 zc = zval(s, u1[t].x, u1[t].y, v1r[t].x, v1r[t].y, rs1, nm1);
            const float2 zd = zval(s, u1[t].z, u1[t].w, v1r[t].z, v1r[t].w, rs1, nm1);

            uint32_t ah[4];
            ah[0] = pack_h2(za.x, za.y);   // row q,   k-lo
            ah[1] = pack_h2(zc.x, zc.y);   // row q+8, k-lo
            ah[2] = pack_h2(zb.x, zb.y);   // row q,   k-hi
            ah[3] = pack_h2(zd.x, zd.y);   // row q+8, k-hi

            const uint32_t sw = (uint32_t)((((ks * 2 + pday) ^ x7)) << 4);
            uint32_t bh[8];
            ldsm4(bhiB + sw,        bh[0], bh[1], bh[2], bh[3]);   // nt 0,1
            ldsm4(bhiB + sw + 8192, bh[4], bh[5], bh[6], bh[7]);   // nt 2,3

            #pragma unroll
            for (int nt = 0; nt < 4; nt++)
                mma16816(acc[nt], ah, bh[2 * nt], bh[2 * nt + 1]);
        }

        // ---- epilogue: relu + W2 dot (bc/w2 from smem), quad reduce ----
        const int c = cq * 2;
        float pp0 = 0.f, pp1 = 0.f;
        #pragma unroll
        for (int nt = 0; nt < 4; nt++) {
            const float bcx = bc_s[nt * 8 + c], bcy = bc_s[nt * 8 + c + 1];
            const float w2x = w2_s[nt * 8 + c], w2y = w2_s[nt * 8 + c + 1];
            pp0 = fmaf(fmaxf(acc[nt][0] + bcx, 0.f), w2x, pp0);
            pp0 = fmaf(fmaxf(acc[nt][1] + bcy, 0.f), w2y, pp0);
            pp1 = fmaf(fmaxf(acc[nt][2] + bcx, 0.f), w2x, pp1);
            pp1 = fmaf(fmaxf(acc[nt][3] + bcy, 0.f), w2y, pp1);
        }
        pp0 += __shfl_xor_sync(0xffffffffu, pp0, 1);
        pp0 += __shfl_xor_sync(0xffffffffu, pp0, 2);
        pp1 += __shfl_xor_sync(0xffffffffu, pp1, 1);
        pp1 += __shfl_xor_sync(0xffffffffu, pp1, 2);
        if (cq == 0) {
            if (v0) out[e0] = pp0 + b2v;
            if (v1) out[e1] = pp1 + b2v;
        }
    }
}

extern "C" void kernel_launch(void* const* d_in, const int* in_sizes, int n_in,
                              void* d_out, int out_size)
{
    const float* h     = (const float*)d_in[0];
    const void*  ep    = d_in[1];
    const float* gamma = (const float*)d_in[2];
    const float* beta  = (const float*)d_in[3];
    const float* W1    = (const float*)d_in[4];
    const float* b1    = (const float*)d_in[5];
    const float* W2    = (const float*)d_in[6];
    const float* b2    = (const float*)d_in[7];
    float* out = (float*)d_out;
    const int E = out_size;
    const int nGroups = (E + 15) / 16;

    int dev = 0, sms = 148;
    cudaGetDevice(&dev);
    cudaDeviceGetAttribute(&sms, cudaDevAttrMultiProcessorCount, dev);
    int grid = sms * 4;
    const int maxg = (nGroups + (NTHREADS / 32) - 1) / (NTHREADS / 32);
    if (grid > maxg) grid = maxg;

    edgehead_mma<<<grid, NTHREADS>>>(h, ep, gamma, beta, W1, b1, W2, b2,
                                     out, E, nGroups);
}